// round 14
// baseline (speedup 1.0000x reference)
#include <cuda_runtime.h>
#include <cuda_fp16.h>
#include <cstdint>
#include <cstdio>

// ------------------------------------------------------------------
// Problem constants
// ------------------------------------------------------------------
#define B_DIM   8192
#define IN_DIM  2048
#define H_DIM   2048
#define OUT_DIM 512
#define DEGP1   5
#define K_TOT (IN_DIM * DEGP1)   // 10240 (both layers)
#define BN_EPS 1e-5f
#define WSCALE 256.0f
#define INV_WSCALE (1.0f / 256.0f)
#define NSPLIT 2                 // GEMM1 split-K factor
#define RED_BLKS 256             // reduce/BN row-blocks (B/32)

// ------------------------------------------------------------------
// Scratch (device globals; no runtime allocation)
// ------------------------------------------------------------------
__device__ __half g_Aexp[(size_t)B_DIM * K_TOT];      // expanded activations
__device__ __half g_W1f [(size_t)H_DIM * K_TOT];      // fused W1 (fp16, x256)
__device__ __half g_W2f [(size_t)OUT_DIM * K_TOT];    // fused W2 (fp16, x256)
__device__ __half g_H1h [(size_t)B_DIM * H_DIM];      // layer-1 pre-BN output
__device__ __half g_splitC[(size_t)NSPLIT * B_DIM * H_DIM]; // GEMM1 fp16 partials
__device__ float  g_c1d0[(size_t)H_DIM * IN_DIM];
__device__ float  g_c2d0[(size_t)OUT_DIM * H_DIM];
__device__ float  g_bias1[H_DIM];
__device__ float  g_bias2[OUT_DIM];
__device__ float  g_partS [RED_BLKS * H_DIM];
__device__ float  g_partS2[RED_BLKS * H_DIM];
__device__ float  g_bnScale[H_DIM];
__device__ float  g_bnShift[H_DIM];

// ------------------------------------------------------------------
// helpers
// ------------------------------------------------------------------
__device__ __forceinline__ void ldsm_x4(uint32_t& r0, uint32_t& r1,
                                        uint32_t& r2, uint32_t& r3, uint32_t addr) {
    asm volatile("ldmatrix.sync.aligned.m8n8.x4.shared.b16 {%0,%1,%2,%3}, [%4];"
                 : "=r"(r0), "=r"(r1), "=r"(r2), "=r"(r3) : "r"(addr));
}

__device__ __forceinline__ float tanh_fast(float x) {
    float r;
    asm("tanh.approx.f32 %0, %1;" : "=f"(r) : "f"(x));
    return r;
}

// ------------------------------------------------------------------
// Coefficient fusion via smem transpose + base-W block (merged).
// ------------------------------------------------------------------
__global__ void fuse_c_kernel(const float* __restrict__ c,
                              const float* __restrict__ s,
                              const float* __restrict__ w,
                              __half* __restrict__ Wf,
                              float* __restrict__ cd0,
                              int In, int Hh) {
    __shared__ float sm[160][33];
    const int tid = threadIdx.x;
    const int i0 = blockIdx.x * 32;
    const int h0 = blockIdx.y * 32;

    for (int e = tid; e < 32 * 160; e += 256) {
        int ii  = e / 160;
        int pos = e % 160;
        sm[pos][ii] = c[(size_t)(i0 + ii) * Hh * DEGP1 + (size_t)h0 * DEGP1 + pos];
    }
    __syncthreads();

    const int lane = tid & 31;
    for (int hl = tid >> 5; hl < 32; hl += 8) {
        float sv = s[h0 + hl];
        cd0[(size_t)(h0 + hl) * In + i0 + lane] = sv * sm[hl * DEGP1][lane];
        __half* wrow = Wf + (size_t)(h0 + hl) * (In * DEGP1);
        wrow[i0 + lane] =
            __float2half_rn(WSCALE * w[(size_t)(h0 + hl) * In + i0 + lane]);
#pragma unroll
        for (int d = 1; d < DEGP1; ++d)
            wrow[d * In + i0 + lane] =
                __float2half_rn(WSCALE * sv * sm[hl * DEGP1 + d][lane]);
    }
}

// bias[o] = b[o] + sum_j staged[o*len + j]
__global__ void bias_reduce_kernel(const float* __restrict__ staged,
                                   const float* __restrict__ b,
                                   float* __restrict__ dst, int len) {
    __shared__ float red[256];
    int o = blockIdx.x;
    const float* src = staged + (size_t)o * len;
    float s = 0.f;
    for (int j = threadIdx.x; j < len; j += 256) s += src[j];
    red[threadIdx.x] = s;
    __syncthreads();
    for (int st = 128; st > 0; st >>= 1) {
        if (threadIdx.x < st) red[threadIdx.x] += red[threadIdx.x + st];
        __syncthreads();
    }
    if (threadIdx.x == 0) dst[o] = b[o] + red[0];
}

// ------------------------------------------------------------------
// Chebyshev expansion
// ------------------------------------------------------------------
__global__ void expand_x_kernel(const float* __restrict__ X) {
    long idx = (long)blockIdx.x * blockDim.x + threadIdx.x;
    if (idx >= (long)B_DIM * IN_DIM / 2) return;
    int r  = (int)(idx / (IN_DIM / 2));
    int cp = (int)(idx % (IN_DIM / 2));
    float2 xv = reinterpret_cast<const float2*>(X)[idx];

    float t0 = tanh_fast(xv.x), t1 = tanh_fast(xv.y);
    float a2 = 2.f * t0 * t0 - 1.f,  b2 = 2.f * t1 * t1 - 1.f;
    float a3 = 2.f * t0 * a2 - t0,   b3 = 2.f * t1 * b2 - t1;
    float a4 = 2.f * t0 * a3 - a2,   b4 = 2.f * t1 * b3 - b2;

    __half* dst = g_Aexp + (size_t)r * K_TOT;
    reinterpret_cast<__half2*>(dst)[cp]              = __floats2half2_rn(xv.x, xv.y);
    reinterpret_cast<__half2*>(dst + IN_DIM)[cp]     = __floats2half2_rn(t0, t1);
    reinterpret_cast<__half2*>(dst + 2 * IN_DIM)[cp] = __floats2half2_rn(a2, b2);
    reinterpret_cast<__half2*>(dst + 3 * IN_DIM)[cp] = __floats2half2_rn(a3, b3);
    reinterpret_cast<__half2*>(dst + 4 * IN_DIM)[cp] = __floats2half2_rn(a4, b4);
}

__global__ void expand_h_kernel() {
    long idx = (long)blockIdx.x * blockDim.x + threadIdx.x;
    if (idx >= (long)B_DIM * H_DIM / 2) return;
    int r  = (int)(idx / (H_DIM / 2));
    int cp = (int)(idx % (H_DIM / 2));
    __half2 hv = reinterpret_cast<const __half2*>(g_H1h)[idx];
    float2 sc = reinterpret_cast<const float2*>(g_bnScale)[cp];
    float2 sh = reinterpret_cast<const float2*>(g_bnShift)[cp];
    float y0 = fmaf(sc.x, __half2float(hv.x), sh.x);
    float y1 = fmaf(sc.y, __half2float(hv.y), sh.y);

    float t0 = tanh_fast(y0), t1 = tanh_fast(y1);
    float a2 = 2.f * t0 * t0 - 1.f,  b2 = 2.f * t1 * t1 - 1.f;
    float a3 = 2.f * t0 * a2 - t0,   b3 = 2.f * t1 * b2 - t1;
    float a4 = 2.f * t0 * a3 - a2,   b4 = 2.f * t1 * b3 - b2;

    __half* dst = g_Aexp + (size_t)r * K_TOT;
    reinterpret_cast<__half2*>(dst)[cp]             = __floats2half2_rn(y0, y1);
    reinterpret_cast<__half2*>(dst + H_DIM)[cp]     = __floats2half2_rn(t0, t1);
    reinterpret_cast<__half2*>(dst + 2 * H_DIM)[cp] = __floats2half2_rn(a2, b2);
    reinterpret_cast<__half2*>(dst + 3 * H_DIM)[cp] = __floats2half2_rn(a3, b3);
    reinterpret_cast<__half2*>(dst + 4 * H_DIM)[cp] = __floats2half2_rn(a4, b4);
}

// ------------------------------------------------------------------
// Split-K reduce (fp16 partials) + bias + H1h store + BN partials.
// ------------------------------------------------------------------
__global__ void reduce_bn_kernel(const float* __restrict__ bias) {
    const int cp = blockIdx.x * 256 + threadIdx.x;
    const int r0 = blockIdx.y * (B_DIM / RED_BLKS);
    const float2 bb = reinterpret_cast<const float2*>(bias)[cp];
    const __half2* P0 = reinterpret_cast<const __half2*>(g_splitC);
    const __half2* P1 = reinterpret_cast<const __half2*>(
        g_splitC + (size_t)B_DIM * H_DIM);
    float s0 = 0.f, s1 = 0.f, q0 = 0.f, q1 = 0.f;
#pragma unroll 4
    for (int r = 0; r < B_DIM / RED_BLKS; ++r) {
        size_t off = (size_t)(r0 + r) * (H_DIM / 2) + cp;
        __half2 p0 = P0[off];
        __half2 p1 = P1[off];
        float h0 = __half2float(p0.x) + __half2float(p1.x) + bb.x;
        float h1 = __half2float(p0.y) + __half2float(p1.y) + bb.y;
        reinterpret_cast<__half2*>(g_H1h)[off] = __floats2half2_rn(h0, h1);
        s0 += h0; s1 += h1;
        q0 += h0 * h0; q1 += h1 * h1;
    }
    reinterpret_cast<float2*>(g_partS  + blockIdx.y * H_DIM)[cp] = make_float2(s0, s1);
    reinterpret_cast<float2*>(g_partS2 + blockIdx.y * H_DIM)[cp] = make_float2(q0, q1);
}

__global__ void bn_fin_kernel(const float* __restrict__ gamma,
                              const float* __restrict__ beta) {
    int col = blockIdx.x * blockDim.x + threadIdx.x;
    if (col >= H_DIM) return;
    float s = 0.f, s2 = 0.f;
    for (int p = 0; p < RED_BLKS; ++p) {
        s  += g_partS [p * H_DIM + col];
        s2 += g_partS2[p * H_DIM + col];
    }
    float invB = 1.f / (float)B_DIM;
    float mu  = s * invB;
    float var = s2 * invB - mu * mu;
    float inv = rsqrtf(var + BN_EPS);
    float sc  = gamma[col] * inv;
    g_bnScale[col] = sc;
    g_bnShift[col] = beta[col] - mu * sc;
}

// ------------------------------------------------------------------
// fp16 tensor-core GEMM: 128x128 block tile, FOUR warps (128 threads),
// warp tile 64x64 (MI=4, NI=8) -> 33% fewer LDSM bytes per MAC.
// GBK=64, 3-stage cp.async, ldmatrix.x4, m16n8k16 fp32 accum, 2 CTAs/SM.
// RAW=true : scaled fp16 partials (split-K along blockIdx.z).
// RAW=false: C = acc*INV_WSCALE + bias (fp32 out).
// ------------------------------------------------------------------
#define GBM 128
#define GBN 128
#define GBK 64
#define GSTAGES 3
#define LDP 72                                     // GBK + 8 pad
#define A_STG (GBM * LDP)
#define B_STG (GBN * LDP)
#define GEMM_SMEM (GSTAGES * (A_STG + B_STG) * 2)  // 110592 B

template <typename OutT, bool RAW>
__global__ void __launch_bounds__(128, 2)
gemm_fp16_kernel(const __half* __restrict__ A, const __half* __restrict__ B,
                 const float* __restrict__ bias, OutT* __restrict__ C,
                 int N, int lda, int kCount, size_t cStride) {
    constexpr int MI = 4;
    constexpr int NI = 8;
    constexpr int WN = 64;

    extern __shared__ __half smem[];
    __half* As = smem;
    __half* Bs = smem + GSTAGES * A_STG;

    const int tid  = threadIdx.x;
    const int lane = tid & 31;
    const int warp = tid >> 5;          // 0..3
    const int wm = warp >> 1;           // 0..1 (64-row warp tiles)
    const int wn = warp & 1;            // 0..1 (64-col warp tiles)

    const int bM = blockIdx.y * GBM;
    const int bN = blockIdx.x * GBN;
    const int kOff = blockIdx.z * kCount;

    const __half* Ag = A + (size_t)bM * lda + kOff;
    const __half* Bg = B + (size_t)bN * lda + kOff;
    OutT* Cg = C + (size_t)blockIdx.z * cStride;

    const int ldr = tid >> 3;           // 0..15
    const int ldc = (tid & 7) * 8;      // 8 halves = 16B

    uint32_t asBase = (uint32_t)__cvta_generic_to_shared(As);
    uint32_t bsBase = (uint32_t)__cvta_generic_to_shared(Bs);

    auto loadTile = [&](int stage, int kt) {
        const __half* ga = Ag + (size_t)ldr * lda + kt * GBK + ldc;
        const __half* gb = Bg + (size_t)ldr * lda + kt * GBK + ldc;
        uint32_t sa  = asBase + (uint32_t)(((stage * GBM + ldr) * LDP + ldc) * 2);
        uint32_t sbp = bsBase + (uint32_t)(((stage * GBN + ldr) * LDP + ldc) * 2);
#pragma unroll
        for (int i = 0; i < 8; ++i)     // 8 x 16 rows = 128
            asm volatile("cp.async.cg.shared.global [%0], [%1], 16;\n"
                         :: "r"(sa + i * 16 * LDP * 2), "l"(ga + (size_t)i * 16 * lda));
#pragma unroll
        for (int i = 0; i < 8; ++i)
            asm volatile("cp.async.cg.shared.global [%0], [%1], 16;\n"
                         :: "r"(sbp + i * 16 * LDP * 2), "l"(gb + (size_t)i * 16 * lda));
    };

    float acc[MI][NI][4];
#pragma unroll
    for (int mi = 0; mi < MI; ++mi)
#pragma unroll
        for (int ni = 0; ni < NI; ++ni)
#pragma unroll
            for (int r = 0; r < 4; ++r) acc[mi][ni][r] = 0.f;

    const int KT = kCount / GBK;
#pragma unroll
    for (int s = 0; s < GSTAGES - 1; ++s) {
        loadTile(s, s);
        asm volatile("cp.async.commit_group;\n");
    }

    const int jj = lane >> 3;
    const int lr = lane & 7;
    uint32_t aAddr[MI];
#pragma unroll
    for (int mi = 0; mi < MI; ++mi) {
        int row = wm * 64 + mi * 16 + ((jj & 1) << 3) + lr;
        aAddr[mi] = asBase + (uint32_t)((row * LDP) * 2 + ((jj >> 1) << 4));
    }
    uint32_t bAddr[NI / 2];
#pragma unroll
    for (int p = 0; p < NI / 2; ++p) {
        int row = wn * WN + p * 16 + ((jj >> 1) << 3) + lr;
        bAddr[p] = bsBase + (uint32_t)((row * LDP) * 2 + ((jj & 1) << 4));
    }

    for (int kt = 0; kt < KT; ++kt) {
        asm volatile("cp.async.wait_group %0;\n" :: "n"(GSTAGES - 2));
        __syncthreads();
        int s = kt % GSTAGES;
        int nkt = kt + GSTAGES - 1;
        if (nkt < KT) loadTile(nkt % GSTAGES, nkt);
        asm volatile("cp.async.commit_group;\n");

        const uint32_t aStg = (uint32_t)(s * A_STG * 2);
        const uint32_t bStg = (uint32_t)(s * B_STG * 2);
#pragma unroll
        for (int kk = 0; kk < GBK / 16; ++kk) {
            const uint32_t kOff2 = kk * 32;
            uint32_t af[MI][4], bf[NI][2];
#pragma unroll
            for (int mi = 0; mi < MI; ++mi)
                ldsm_x4(af[mi][0], af[mi][1], af[mi][2], af[mi][3],
                        aAddr[mi] + aStg + kOff2);
#pragma unroll
            for (int p = 0; p < NI / 2; ++p)
                ldsm_x4(bf[2 * p][0], bf[2 * p][1], bf[2 * p + 1][0], bf[2 * p + 1][1],
                        bAddr[p] + bStg + kOff2);
#pragma unroll
            for (int mi = 0; mi < MI; ++mi)
#pragma unroll
                for (int ni = 0; ni < NI; ++ni) {
                    asm volatile(
                        "mma.sync.aligned.m16n8k16.row.col.f32.f16.f16.f32 "
                        "{%0,%1,%2,%3}, {%4,%5,%6,%7}, {%8,%9}, {%0,%1,%2,%3};\n"
                        : "+f"(acc[mi][ni][0]), "+f"(acc[mi][ni][1]),
                          "+f"(acc[mi][ni][2]), "+f"(acc[mi][ni][3])
                        : "r"(af[mi][0]), "r"(af[mi][1]), "r"(af[mi][2]), "r"(af[mi][3]),
                          "r"(bf[ni][0]), "r"(bf[ni][1]));
                }
        }
    }

    // ---------------- epilogue ----------------
#pragma unroll
    for (int mi = 0; mi < MI; ++mi) {
        int r0 = bM + wm * 64 + mi * 16 + (lane >> 2);
#pragma unroll
        for (int ni = 0; ni < NI; ++ni) {
            int c = bN + wn * WN + ni * 8 + (lane & 3) * 2;
            if constexpr (RAW) {
                *reinterpret_cast<__half2*>(&Cg[(size_t)r0 * N + c]) =
                    __floats2half2_rn(acc[mi][ni][0] * INV_WSCALE,
                                      acc[mi][ni][1] * INV_WSCALE);
                *reinterpret_cast<__half2*>(&Cg[(size_t)(r0 + 8) * N + c]) =
                    __floats2half2_rn(acc[mi][ni][2] * INV_WSCALE,
                                      acc[mi][ni][3] * INV_WSCALE);
            } else {
                float b0 = bias[c], b1v = bias[c + 1];
                float f00 = fmaf(acc[mi][ni][0], INV_WSCALE, b0);
                float f01 = fmaf(acc[mi][ni][1], INV_WSCALE, b1v);
                float f10 = fmaf(acc[mi][ni][2], INV_WSCALE, b0);
                float f11 = fmaf(acc[mi][ni][3], INV_WSCALE, b1v);
                *reinterpret_cast<float2*>(&Cg[(size_t)r0 * N + c]) =
                    make_float2(f00, f01);
                *reinterpret_cast<float2*>(&Cg[(size_t)(r0 + 8) * N + c]) =
                    make_float2(f10, f11);
            }
        }
    }
}

// ------------------------------------------------------------------
// launch
// ------------------------------------------------------------------
extern "C" void kernel_launch(void* const* d_in, const int* in_sizes, int n_in,
                              void* d_out, int out_size) {
    const float* x     = (const float*)d_in[0];
    const float* w1    = (const float*)d_in[1];
    const float* b1    = (const float*)d_in[2];
    const float* c1    = (const float*)d_in[3];
    const float* s1    = (const float*)d_in[4];
    const float* gamma = (const float*)d_in[5];
    const float* beta  = (const float*)d_in[6];
    const float* w2    = (const float*)d_in[7];
    const float* b2    = (const float*)d_in[8];
    const float* c2    = (const float*)d_in[9];
    const float* s2    = (const float*)d_in[10];
    float* out = (float*)d_out;

    cudaFuncSetAttribute((const void*)gemm_fp16_kernel<__half, true>,
                         cudaFuncAttributeMaxDynamicSharedMemorySize, GEMM_SMEM);
    cudaFuncSetAttribute((const void*)gemm_fp16_kernel<float, false>,
                         cudaFuncAttributeMaxDynamicSharedMemorySize, GEMM_SMEM);

    void *pA, *pW1, *pW2, *pSC, *pB1, *pB2, *pC1d0, *pC2d0;
    cudaGetSymbolAddress(&pA,    g_Aexp);
    cudaGetSymbolAddress(&pW1,   g_W1f);
    cudaGetSymbolAddress(&pW2,   g_W2f);
    cudaGetSymbolAddress(&pSC,   g_splitC);
    cudaGetSymbolAddress(&pB1,   g_bias1);
    cudaGetSymbolAddress(&pB2,   g_bias2);
    cudaGetSymbolAddress(&pC1d0, g_c1d0);
    cudaGetSymbolAddress(&pC2d0, g_c2d0);

    // 1: layer-1 weight fusion (incl. base block)
    {
        dim3 g1(IN_DIM / 32, H_DIM / 32);
        fuse_c_kernel<<<g1, 256>>>(c1, s1, w1, (__half*)pW1, (float*)pC1d0,
                                   IN_DIM, H_DIM);
    }
    // 2: layer-1 bias
    bias_reduce_kernel<<<H_DIM, 256>>>((const float*)pC1d0, b1, (float*)pB1, IN_DIM);
    // 3: expansion of x
    expand_x_kernel<<<(B_DIM * IN_DIM / 2 + 255) / 256, 256>>>(x);
    // 4: GEMM1 split-K=2 (2048 CTAs -> 98.8% wave utilization)
    {
        dim3 grid(H_DIM / GBN, B_DIM / GBM, NSPLIT);   // (16, 64, 2)
        gemm_fp16_kernel<__half, true><<<grid, 128, GEMM_SMEM>>>(
            (const __half*)pA, (const __half*)pW1, nullptr,
            (__half*)pSC, H_DIM, K_TOT, K_TOT / NSPLIT,
            (size_t)B_DIM * H_DIM);
    }
    // 5: split reduce + bias + H1h + BN partials
    reduce_bn_kernel<<<dim3(H_DIM / 512, RED_BLKS), 256>>>((const float*)pB1);
    // 6: layer-2 weight fusion
    {
        dim3 g2(H_DIM / 32, OUT_DIM / 32);
        fuse_c_kernel<<<g2, 256>>>(c2, s2, w2, (__half*)pW2, (float*)pC2d0,
                                   H_DIM, OUT_DIM);
    }
    // 7: layer-2 bias
    bias_reduce_kernel<<<OUT_DIM, 256>>>((const float*)pC2d0, b2, (float*)pB2, H_DIM);
    // 8: BN finalize
    bn_fin_kernel<<<H_DIM / 256, 256>>>(gamma, beta);
    // 9: expansion of h
    expand_h_kernel<<<(B_DIM * H_DIM / 2 + 255) / 256, 256>>>();
    // 10: GEMM2 (128x128, 256 CTAs, single wave)
    {
        dim3 grid(OUT_DIM / GBN, B_DIM / GBM, 1);      // (4, 64, 1)
        gemm_fp16_kernel<float, false><<<grid, 128, GEMM_SMEM>>>(
            (const __half*)pA, (const __half*)pW2, (const float*)pB2,
            out, OUT_DIM, K_TOT, K_TOT, 0);
    }
}

// round 15
// speedup vs baseline: 1.0533x; 1.0533x over previous
#include <cuda_runtime.h>
#include <cuda_fp16.h>
#include <cstdint>
#include <cstdio>

// ------------------------------------------------------------------
// Problem constants
// ------------------------------------------------------------------
#define B_DIM   8192
#define IN_DIM  2048
#define H_DIM   2048
#define OUT_DIM 512
#define DEGP1   5
#define K_TOT (IN_DIM * DEGP1)   // 10240 (both layers)
#define BN_EPS 1e-5f
#define WSCALE 256.0f
#define INV_WSCALE (1.0f / 256.0f)
#define NSPLIT 2                 // GEMM1 split-K factor
#define NSPLIT2 8                // GEMM2 split-K factor (2048 CTAs -> 98.8% util)
#define RED_BLKS 256             // reduce/BN row-blocks (B/32)

// ------------------------------------------------------------------
// Scratch (device globals; no runtime allocation)
// g_splitC holds GEMM1 partials (2 x B x H) then is reused for GEMM2
// partials (8 x B x OUT) -- identical size: 33.5M halves.
// ------------------------------------------------------------------
__device__ __half g_Aexp[(size_t)B_DIM * K_TOT];      // expanded activations
__device__ __half g_W1f [(size_t)H_DIM * K_TOT];      // fused W1 (fp16, x256)
__device__ __half g_W2f [(size_t)OUT_DIM * K_TOT];    // fused W2 (fp16, x256)
__device__ __half g_H1h [(size_t)B_DIM * H_DIM];      // layer-1 pre-BN output
__device__ __half g_splitC[(size_t)NSPLIT * B_DIM * H_DIM]; // split-K partials
__device__ float  g_c1d0[(size_t)H_DIM * IN_DIM];
__device__ float  g_c2d0[(size_t)OUT_DIM * H_DIM];
__device__ float  g_bias1[H_DIM];
__device__ float  g_bias2[OUT_DIM];
__device__ float  g_partS [RED_BLKS * H_DIM];
__device__ float  g_partS2[RED_BLKS * H_DIM];
__device__ float  g_bnScale[H_DIM];
__device__ float  g_bnShift[H_DIM];

// ------------------------------------------------------------------
// helpers
// ------------------------------------------------------------------
__device__ __forceinline__ void ldsm_x4(uint32_t& r0, uint32_t& r1,
                                        uint32_t& r2, uint32_t& r3, uint32_t addr) {
    asm volatile("ldmatrix.sync.aligned.m8n8.x4.shared.b16 {%0,%1,%2,%3}, [%4];"
                 : "=r"(r0), "=r"(r1), "=r"(r2), "=r"(r3) : "r"(addr));
}

__device__ __forceinline__ float tanh_fast(float x) {
    float r;
    asm("tanh.approx.f32 %0, %1;" : "=f"(r) : "f"(x));
    return r;
}

// ------------------------------------------------------------------
// Coefficient fusion via smem transpose + base-W block (merged).
// ------------------------------------------------------------------
__global__ void fuse_c_kernel(const float* __restrict__ c,
                              const float* __restrict__ s,
                              const float* __restrict__ w,
                              __half* __restrict__ Wf,
                              float* __restrict__ cd0,
                              int In, int Hh) {
    __shared__ float sm[160][33];
    const int tid = threadIdx.x;
    const int i0 = blockIdx.x * 32;
    const int h0 = blockIdx.y * 32;

    for (int e = tid; e < 32 * 160; e += 256) {
        int ii  = e / 160;
        int pos = e % 160;
        sm[pos][ii] = c[(size_t)(i0 + ii) * Hh * DEGP1 + (size_t)h0 * DEGP1 + pos];
    }
    __syncthreads();

    const int lane = tid & 31;
    for (int hl = tid >> 5; hl < 32; hl += 8) {
        float sv = s[h0 + hl];
        cd0[(size_t)(h0 + hl) * In + i0 + lane] = sv * sm[hl * DEGP1][lane];
        __half* wrow = Wf + (size_t)(h0 + hl) * (In * DEGP1);
        wrow[i0 + lane] =
            __float2half_rn(WSCALE * w[(size_t)(h0 + hl) * In + i0 + lane]);
#pragma unroll
        for (int d = 1; d < DEGP1; ++d)
            wrow[d * In + i0 + lane] =
                __float2half_rn(WSCALE * sv * sm[hl * DEGP1 + d][lane]);
    }
}

// bias[o] = b[o] + sum_j staged[o*len + j]
__global__ void bias_reduce_kernel(const float* __restrict__ staged,
                                   const float* __restrict__ b,
                                   float* __restrict__ dst, int len) {
    __shared__ float red[256];
    int o = blockIdx.x;
    const float* src = staged + (size_t)o * len;
    float s = 0.f;
    for (int j = threadIdx.x; j < len; j += 256) s += src[j];
    red[threadIdx.x] = s;
    __syncthreads();
    for (int st = 128; st > 0; st >>= 1) {
        if (threadIdx.x < st) red[threadIdx.x] += red[threadIdx.x + st];
        __syncthreads();
    }
    if (threadIdx.x == 0) dst[o] = b[o] + red[0];
}

// ------------------------------------------------------------------
// Chebyshev expansion
// ------------------------------------------------------------------
__global__ void expand_x_kernel(const float* __restrict__ X) {
    long idx = (long)blockIdx.x * blockDim.x + threadIdx.x;
    if (idx >= (long)B_DIM * IN_DIM / 2) return;
    int r  = (int)(idx / (IN_DIM / 2));
    int cp = (int)(idx % (IN_DIM / 2));
    float2 xv = reinterpret_cast<const float2*>(X)[idx];

    float t0 = tanh_fast(xv.x), t1 = tanh_fast(xv.y);
    float a2 = 2.f * t0 * t0 - 1.f,  b2 = 2.f * t1 * t1 - 1.f;
    float a3 = 2.f * t0 * a2 - t0,   b3 = 2.f * t1 * b2 - t1;
    float a4 = 2.f * t0 * a3 - a2,   b4 = 2.f * t1 * b3 - b2;

    __half* dst = g_Aexp + (size_t)r * K_TOT;
    reinterpret_cast<__half2*>(dst)[cp]              = __floats2half2_rn(xv.x, xv.y);
    reinterpret_cast<__half2*>(dst + IN_DIM)[cp]     = __floats2half2_rn(t0, t1);
    reinterpret_cast<__half2*>(dst + 2 * IN_DIM)[cp] = __floats2half2_rn(a2, b2);
    reinterpret_cast<__half2*>(dst + 3 * IN_DIM)[cp] = __floats2half2_rn(a3, b3);
    reinterpret_cast<__half2*>(dst + 4 * IN_DIM)[cp] = __floats2half2_rn(a4, b4);
}

__global__ void expand_h_kernel() {
    long idx = (long)blockIdx.x * blockDim.x + threadIdx.x;
    if (idx >= (long)B_DIM * H_DIM / 2) return;
    int r  = (int)(idx / (H_DIM / 2));
    int cp = (int)(idx % (H_DIM / 2));
    __half2 hv = reinterpret_cast<const __half2*>(g_H1h)[idx];
    float2 sc = reinterpret_cast<const float2*>(g_bnScale)[cp];
    float2 sh = reinterpret_cast<const float2*>(g_bnShift)[cp];
    float y0 = fmaf(sc.x, __half2float(hv.x), sh.x);
    float y1 = fmaf(sc.y, __half2float(hv.y), sh.y);

    float t0 = tanh_fast(y0), t1 = tanh_fast(y1);
    float a2 = 2.f * t0 * t0 - 1.f,  b2 = 2.f * t1 * t1 - 1.f;
    float a3 = 2.f * t0 * a2 - t0,   b3 = 2.f * t1 * b2 - t1;
    float a4 = 2.f * t0 * a3 - a2,   b4 = 2.f * t1 * b3 - b2;

    __half* dst = g_Aexp + (size_t)r * K_TOT;
    reinterpret_cast<__half2*>(dst)[cp]             = __floats2half2_rn(y0, y1);
    reinterpret_cast<__half2*>(dst + H_DIM)[cp]     = __floats2half2_rn(t0, t1);
    reinterpret_cast<__half2*>(dst + 2 * H_DIM)[cp] = __floats2half2_rn(a2, b2);
    reinterpret_cast<__half2*>(dst + 3 * H_DIM)[cp] = __floats2half2_rn(a3, b3);
    reinterpret_cast<__half2*>(dst + 4 * H_DIM)[cp] = __floats2half2_rn(a4, b4);
}

// ------------------------------------------------------------------
// GEMM1 split-K reduce (fp16 partials) + bias + H1h + BN partials.
// ------------------------------------------------------------------
__global__ void reduce_bn_kernel(const float* __restrict__ bias) {
    const int cp = blockIdx.x * 256 + threadIdx.x;
    const int r0 = blockIdx.y * (B_DIM / RED_BLKS);
    const float2 bb = reinterpret_cast<const float2*>(bias)[cp];
    const __half2* P0 = reinterpret_cast<const __half2*>(g_splitC);
    const __half2* P1 = reinterpret_cast<const __half2*>(
        g_splitC + (size_t)B_DIM * H_DIM);
    float s0 = 0.f, s1 = 0.f, q0 = 0.f, q1 = 0.f;
#pragma unroll 4
    for (int r = 0; r < B_DIM / RED_BLKS; ++r) {
        size_t off = (size_t)(r0 + r) * (H_DIM / 2) + cp;
        __half2 p0 = P0[off];
        __half2 p1 = P1[off];
        float h0 = __half2float(p0.x) + __half2float(p1.x) + bb.x;
        float h1 = __half2float(p0.y) + __half2float(p1.y) + bb.y;
        reinterpret_cast<__half2*>(g_H1h)[off] = __floats2half2_rn(h0, h1);
        s0 += h0; s1 += h1;
        q0 += h0 * h0; q1 += h1 * h1;
    }
    reinterpret_cast<float2*>(g_partS  + blockIdx.y * H_DIM)[cp] = make_float2(s0, s1);
    reinterpret_cast<float2*>(g_partS2 + blockIdx.y * H_DIM)[cp] = make_float2(q0, q1);
}

__global__ void bn_fin_kernel(const float* __restrict__ gamma,
                              const float* __restrict__ beta) {
    int col = blockIdx.x * blockDim.x + threadIdx.x;
    if (col >= H_DIM) return;
    float s = 0.f, s2 = 0.f;
    for (int p = 0; p < RED_BLKS; ++p) {
        s  += g_partS [p * H_DIM + col];
        s2 += g_partS2[p * H_DIM + col];
    }
    float invB = 1.f / (float)B_DIM;
    float mu  = s * invB;
    float var = s2 * invB - mu * mu;
    float inv = rsqrtf(var + BN_EPS);
    float sc  = gamma[col] * inv;
    g_bnScale[col] = sc;
    g_bnShift[col] = beta[col] - mu * sc;
}

// ------------------------------------------------------------------
// GEMM2 split-K reduce: out = sum_{s=0..7} P_s + bias  (fp32 out)
// grid (B*OUT/2/256), block 256; thread = column pair.
// ------------------------------------------------------------------
__global__ void out_reduce_kernel(const float* __restrict__ bias,
                                  float* __restrict__ out) {
    long idx = (long)blockIdx.x * blockDim.x + threadIdx.x;
    if (idx >= (long)B_DIM * OUT_DIM / 2) return;
    int cp = (int)(idx % (OUT_DIM / 2));
    const float2 bb = reinterpret_cast<const float2*>(bias)[cp];
    const __half2* P = reinterpret_cast<const __half2*>(g_splitC);
    const size_t stride = (size_t)B_DIM * OUT_DIM / 2;
    float s0 = bb.x, s1 = bb.y;
#pragma unroll
    for (int sp = 0; sp < NSPLIT2; ++sp) {
        __half2 p = P[sp * stride + idx];
        s0 += __half2float(p.x);
        s1 += __half2float(p.y);
    }
    reinterpret_cast<float2*>(out)[idx] = make_float2(s0, s1);
}

// ------------------------------------------------------------------
// fp16 tensor-core GEMM, 128x128 tile, 8 warps (64x32 warp tile),
// GBK=64, 3-stage cp.async, ldmatrix.x4, m16n8k16 fp32 accum, 2 CTAs/SM.
// EXACT R13 mainloop (best measured: 63.8% tensor, 885 us).
// Writes scaled fp16 partials (split-K along blockIdx.z).
// ------------------------------------------------------------------
#define GBM 128
#define GBN 128
#define GBK 64
#define GSTAGES 3
#define LDP 72                                     // GBK + 8 pad
#define A_STG (GBM * LDP)
#define B_STG (GBN * LDP)
#define GEMM_SMEM (GSTAGES * (A_STG + B_STG) * 2)  // 110592 B

__global__ void __launch_bounds__(256, 2)
gemm_fp16_kernel(const __half* __restrict__ A, const __half* __restrict__ B,
                 __half* __restrict__ C,
                 int N, int lda, int kCount, size_t cStride) {
    constexpr int MI = 4;
    constexpr int NI = 4;
    constexpr int WN = 32;

    extern __shared__ __half smem[];
    __half* As = smem;
    __half* Bs = smem + GSTAGES * A_STG;

    const int tid  = threadIdx.x;
    const int lane = tid & 31;
    const int warp = tid >> 5;
    const int wm = warp >> 2;
    const int wn = warp & 3;

    const int bM = blockIdx.y * GBM;
    const int bN = blockIdx.x * GBN;
    const int kOff = blockIdx.z * kCount;

    const __half* Ag = A + (size_t)bM * lda + kOff;
    const __half* Bg = B + (size_t)bN * lda + kOff;
    __half* Cg = C + (size_t)blockIdx.z * cStride;

    const int ldr = tid >> 3;
    const int ldc = (tid & 7) * 8;

    uint32_t asBase = (uint32_t)__cvta_generic_to_shared(As);
    uint32_t bsBase = (uint32_t)__cvta_generic_to_shared(Bs);

    auto loadTile = [&](int stage, int kt) {
        const __half* ga = Ag + (size_t)ldr * lda + kt * GBK + ldc;
        const __half* gb = Bg + (size_t)ldr * lda + kt * GBK + ldc;
        uint32_t sa  = asBase + (uint32_t)(((stage * GBM + ldr) * LDP + ldc) * 2);
        uint32_t sbp = bsBase + (uint32_t)(((stage * GBN + ldr) * LDP + ldc) * 2);
#pragma unroll
        for (int i = 0; i < 4; ++i)
            asm volatile("cp.async.cg.shared.global [%0], [%1], 16;\n"
                         :: "r"(sa + i * 32 * LDP * 2), "l"(ga + (size_t)i * 32 * lda));
#pragma unroll
        for (int i = 0; i < 4; ++i)
            asm volatile("cp.async.cg.shared.global [%0], [%1], 16;\n"
                         :: "r"(sbp + i * 32 * LDP * 2), "l"(gb + (size_t)i * 32 * lda));
    };

    float acc[MI][NI][4];
#pragma unroll
    for (int mi = 0; mi < MI; ++mi)
#pragma unroll
        for (int ni = 0; ni < NI; ++ni)
#pragma unroll
            for (int r = 0; r < 4; ++r) acc[mi][ni][r] = 0.f;

    const int KT = kCount / GBK;
#pragma unroll
    for (int s = 0; s < GSTAGES - 1; ++s) {
        loadTile(s, s);
        asm volatile("cp.async.commit_group;\n");
    }

    const int jj = lane >> 3;
    const int lr = lane & 7;
    uint32_t aAddr[MI];
#pragma unroll
    for (int mi = 0; mi < MI; ++mi) {
        int row = wm * 64 + mi * 16 + ((jj & 1) << 3) + lr;
        aAddr[mi] = asBase + (uint32_t)((row * LDP) * 2 + ((jj >> 1) << 4));
    }
    uint32_t bAddr[NI / 2];
#pragma unroll
    for (int p = 0; p < NI / 2; ++p) {
        int row = wn * WN + p * 16 + ((jj >> 1) << 3) + lr;
        bAddr[p] = bsBase + (uint32_t)((row * LDP) * 2 + ((jj & 1) << 4));
    }

    for (int kt = 0; kt < KT; ++kt) {
        asm volatile("cp.async.wait_group %0;\n" :: "n"(GSTAGES - 2));
        __syncthreads();
        int s = kt % GSTAGES;
        int nkt = kt + GSTAGES - 1;
        if (nkt < KT) loadTile(nkt % GSTAGES, nkt);
        asm volatile("cp.async.commit_group;\n");

        const uint32_t aStg = (uint32_t)(s * A_STG * 2);
        const uint32_t bStg = (uint32_t)(s * B_STG * 2);
#pragma unroll
        for (int kk = 0; kk < GBK / 16; ++kk) {
            const uint32_t kOff2 = kk * 32;
            uint32_t af[MI][4], bf[NI][2];
#pragma unroll
            for (int mi = 0; mi < MI; ++mi)
                ldsm_x4(af[mi][0], af[mi][1], af[mi][2], af[mi][3],
                        aAddr[mi] + aStg + kOff2);
#pragma unroll
            for (int p = 0; p < NI / 2; ++p)
                ldsm_x4(bf[2 * p][0], bf[2 * p][1], bf[2 * p + 1][0], bf[2 * p + 1][1],
                        bAddr[p] + bStg + kOff2);
#pragma unroll
            for (int mi = 0; mi < MI; ++mi)
#pragma unroll
                for (int ni = 0; ni < NI; ++ni) {
                    asm volatile(
                        "mma.sync.aligned.m16n8k16.row.col.f32.f16.f16.f32 "
                        "{%0,%1,%2,%3}, {%4,%5,%6,%7}, {%8,%9}, {%0,%1,%2,%3};\n"
                        : "+f"(acc[mi][ni][0]), "+f"(acc[mi][ni][1]),
                          "+f"(acc[mi][ni][2]), "+f"(acc[mi][ni][3])
                        : "r"(af[mi][0]), "r"(af[mi][1]), "r"(af[mi][2]), "r"(af[mi][3]),
                          "r"(bf[ni][0]), "r"(bf[ni][1]));
                }
        }
    }

    // epilogue: scaled fp16 partials (bias added in the reduce pass)
#pragma unroll
    for (int mi = 0; mi < MI; ++mi) {
        int r0 = bM + wm * 64 + mi * 16 + (lane >> 2);
#pragma unroll
        for (int ni = 0; ni < NI; ++ni) {
            int c = bN + wn * WN + ni * 8 + (lane & 3) * 2;
            *reinterpret_cast<__half2*>(&Cg[(size_t)r0 * N + c]) =
                __floats2half2_rn(acc[mi][ni][0] * INV_WSCALE,
                                  acc[mi][ni][1] * INV_WSCALE);
            *reinterpret_cast<__half2*>(&Cg[(size_t)(r0 + 8) * N + c]) =
                __floats2half2_rn(acc[mi][ni][2] * INV_WSCALE,
                                  acc[mi][ni][3] * INV_WSCALE);
        }
    }
}

// ------------------------------------------------------------------
// launch
// ------------------------------------------------------------------
extern "C" void kernel_launch(void* const* d_in, const int* in_sizes, int n_in,
                              void* d_out, int out_size) {
    const float* x     = (const float*)d_in[0];
    const float* w1    = (const float*)d_in[1];
    const float* b1    = (const float*)d_in[2];
    const float* c1    = (const float*)d_in[3];
    const float* s1    = (const float*)d_in[4];
    const float* gamma = (const float*)d_in[5];
    const float* beta  = (const float*)d_in[6];
    const float* w2    = (const float*)d_in[7];
    const float* b2    = (const float*)d_in[8];
    const float* c2    = (const float*)d_in[9];
    const float* s2    = (const float*)d_in[10];
    float* out = (float*)d_out;

    cudaFuncSetAttribute((const void*)gemm_fp16_kernel,
                         cudaFuncAttributeMaxDynamicSharedMemorySize, GEMM_SMEM);

    void *pA, *pW1, *pW2, *pSC, *pB1, *pB2, *pC1d0, *pC2d0;
    cudaGetSymbolAddress(&pA,    g_Aexp);
    cudaGetSymbolAddress(&pW1,   g_W1f);
    cudaGetSymbolAddress(&pW2,   g_W2f);
    cudaGetSymbolAddress(&pSC,   g_splitC);
    cudaGetSymbolAddress(&pB1,   g_bias1);
    cudaGetSymbolAddress(&pB2,   g_bias2);
    cudaGetSymbolAddress(&pC1d0, g_c1d0);
    cudaGetSymbolAddress(&pC2d0, g_c2d0);

    // 1: layer-1 weight fusion (incl. base block)
    {
        dim3 g1(IN_DIM / 32, H_DIM / 32);
        fuse_c_kernel<<<g1, 256>>>(c1, s1, w1, (__half*)pW1, (float*)pC1d0,
                                   IN_DIM, H_DIM);
    }
    // 2: layer-1 bias
    bias_reduce_kernel<<<H_DIM, 256>>>((const float*)pC1d0, b1, (float*)pB1, IN_DIM);
    // 3: expansion of x
    expand_x_kernel<<<(B_DIM * IN_DIM / 2 + 255) / 256, 256>>>(x);
    // 4: GEMM1 split-K=2 (2048 CTAs -> 98.8% wave utilization)
    {
        dim3 grid(H_DIM / GBN, B_DIM / GBM, NSPLIT);   // (16, 64, 2)
        gemm_fp16_kernel<<<grid, 256, GEMM_SMEM>>>(
            (const __half*)pA, (const __half*)pW1,
            (__half*)pSC, H_DIM, K_TOT, K_TOT / NSPLIT,
            (size_t)B_DIM * H_DIM);
    }
    // 5: split reduce + bias + H1h + BN partials
    reduce_bn_kernel<<<dim3(H_DIM / 512, RED_BLKS), 256>>>((const float*)pB1);
    // 6: layer-2 weight fusion
    {
        dim3 g2(H_DIM / 32, OUT_DIM / 32);
        fuse_c_kernel<<<g2, 256>>>(c2, s2, w2, (__half*)pW2, (float*)pC2d0,
                                   H_DIM, OUT_DIM);
    }
    // 7: layer-2 bias
    bias_reduce_kernel<<<OUT_DIM, 256>>>((const float*)pC2d0, b2, (float*)pB2, H_DIM);
    // 8: BN finalize
    bn_fin_kernel<<<H_DIM / 256, 256>>>(gamma, beta);
    // 9: expansion of h
    expand_h_kernel<<<(B_DIM * H_DIM / 2 + 255) / 256, 256>>>();
    // 10: GEMM2 split-K=8 (2048 CTAs -> 98.8% wave utilization)
    {
        dim3 grid(OUT_DIM / GBN, B_DIM / GBM, NSPLIT2); // (4, 64, 8)
        gemm_fp16_kernel<<<grid, 256, GEMM_SMEM>>>(
            (const __half*)pA, (const __half*)pW2,
            (__half*)pSC, OUT_DIM, K_TOT, K_TOT / NSPLIT2,
            (size_t)B_DIM * OUT_DIM);
    }
    // 11: GEMM2 split reduce + bias -> fp32 output
    out_reduce_kernel<<<(B_DIM * OUT_DIM / 2 + 255) / 256, 256>>>(
        (const float*)pB2, out);
}